// round 15
// baseline (speedup 1.0000x reference)
#include <cuda_runtime.h>
#include <math.h>
#include <stdint.h>

#define BSZ 2
#define SEQ 2048
#define DMODEL 1024
#define NH 16
#define HD 64
#define MROWS (BSZ * SEQ)   // 4096
#define NQKV (3 * DMODEL)   // 3072
#define L2E 1.4426950408889634f
#define QSCALE (0.125f * L2E)

// -------- scratch (device globals; no allocation allowed) --------
__device__ float g_A[MROWS * DMODEL];        // tf32-rounded X
__device__ float g_QKV[MROWS * NQKV];        // Q(pre-scaled)|K rounded (V cols unused)
__device__ float g_Vt[BSZ * DMODEL * SEQ];   // V transposed: [b*1024 + h*64+d][s]
__device__ float g_C[MROWS * DMODEL];        // attention output (tf32-rounded)
__device__ float g_WtQKV[NQKV * DMODEL];     // transposed+rounded Wq|Wk|Wv [n][k]
__device__ float g_WtO[DMODEL * DMODEL];     // transposed+rounded Wo       [n][k]
__device__ float g_biasQKV[NQKV];

__device__ __forceinline__ float rna_tf32(float x) {
    uint32_t u;
    asm("cvt.rna.tf32.f32 %0, %1;" : "=r"(u) : "f"(x));
    return __uint_as_float(u);
}
__device__ __forceinline__ float ex2(float x) {
    float r;
    asm("ex2.approx.ftz.f32 %0, %1;" : "=f"(r) : "f"(x));
    return r;
}
__device__ __forceinline__ uint32_t smem_u32(const void* p) {
    uint32_t a;
    asm("{ .reg .u64 t; cvta.to.shared.u64 t, %1; cvt.u32.u64 %0, t; }" : "=r"(a) : "l"(p));
    return a;
}
#define CP_ASYNC16(dst, src) \
    asm volatile("cp.async.ca.shared.global [%0], [%1], 16;" :: "r"(dst), "l"(src))
#define CP_COMMIT() asm volatile("cp.async.commit_group;" ::: "memory")
#define CP_WAIT0()  asm volatile("cp.async.wait_group 0;" ::: "memory")

__device__ __forceinline__ void mma_tf32(float& c0, float& c1, float& c2, float& c3,
                                         uint32_t a0, uint32_t a1, uint32_t a2, uint32_t a3,
                                         uint32_t b0, uint32_t b1) {
    asm volatile(
        "mma.sync.aligned.m16n8k8.row.col.f32.tf32.tf32.f32 "
        "{%0,%1,%2,%3}, {%4,%5,%6,%7}, {%8,%9}, {%0,%1,%2,%3};"
        : "+f"(c0), "+f"(c1), "+f"(c2), "+f"(c3)
        : "r"(a0), "r"(a1), "r"(a2), "r"(a3), "r"(b0), "r"(b1));
}
__device__ __forceinline__ void ldsm_x4(uint32_t& r0, uint32_t& r1, uint32_t& r2, uint32_t& r3,
                                        uint32_t addr) {
    asm volatile("ldmatrix.sync.aligned.m8n8.x4.shared.b16 {%0,%1,%2,%3}, [%4];"
                 : "=r"(r0), "=r"(r1), "=r"(r2), "=r"(r3) : "r"(addr));
}

// ============================================================================
// tf32 mma.sync GEMM: CTA 128x128, 128 thr, 2 CTAs/SM.
// roundC==1: Q cols scaled+rounded -> g_QKV; K cols rounded -> g_QKV;
//            V cols rounded -> g_Vt TRANSPOSED ([b*1024+col-2048][s]).
// ============================================================================
#define BK 32
#define SM_STRIDE 36
#define SMG_A (128 * SM_STRIDE)
#define SMG_STAGE (2 * SMG_A)
#define GEMM_SMEM (2 * SMG_STAGE * 4)

__global__ __launch_bounds__(128, 2) void gemm_mma(
    const float* __restrict__ A, const float* __restrict__ Bt,
    const float* __restrict__ bias, float* __restrict__ C, int Ntot, int roundC)
{
    extern __shared__ float sm[];
    const uint32_t smb = smem_u32(sm);
    const int t    = threadIdx.x;
    const int wid  = t >> 5;
    const int lane = t & 31;
    const int wm   = wid >> 1;
    const int wn   = wid & 1;
    const int g    = lane >> 2;
    const int j    = lane & 3;
    const int bm = blockIdx.y * 128;
    const int bn = blockIdx.x * 128;

    const float* Ag = A  + (size_t)bm * DMODEL;
    const float* Bg = Bt + (size_t)bn * DMODEL;

    float acc[4][8][4];
#pragma unroll
    for (int mt = 0; mt < 4; mt++)
#pragma unroll
        for (int nt = 0; nt < 8; nt++)
#pragma unroll
            for (int r = 0; r < 4; r++) acc[mt][nt][r] = 0.0f;

    uint32_t aoff[4], boff[4];
    {
        const int arow = lane & 15, acol = (lane >> 4) * 4;
#pragma unroll
        for (int mt = 0; mt < 4; mt++)
            aoff[mt] = (uint32_t)(((wm * 64 + mt * 16 + arow) * SM_STRIDE + acol) * 4);
        const int brow = ((lane >> 4) & 1) * 8 + (lane & 7);
        const int bcol = ((lane >> 3) & 1) * 4;
#pragma unroll
        for (int p = 0; p < 4; p++)
            boff[p] = (uint32_t)((SMG_A + (wn * 64 + p * 16 + brow) * SM_STRIDE + bcol) * 4);
    }

    auto issue = [&](int it, int stage) {
        const int kb = it * BK;
        const uint32_t base = smb + (uint32_t)stage * (SMG_STAGE * 4);
#pragma unroll
        for (int jj = 0; jj < 8; jj++) {
            int lin = t + jj * 128;
            int row = lin >> 3, k4 = (lin & 7) * 4;
            CP_ASYNC16(base + (uint32_t)(row * SM_STRIDE + k4) * 4,
                       &Ag[(size_t)row * DMODEL + kb + k4]);
            CP_ASYNC16(base + (uint32_t)(SMG_A + row * SM_STRIDE + k4) * 4,
                       &Bg[(size_t)row * DMODEL + kb + k4]);
        }
        CP_COMMIT();
    };

    const int NITER = DMODEL / BK;
    issue(0, 0);

    for (int it = 0; it < NITER; it++) {
        CP_WAIT0();
        __syncthreads();
        if (it + 1 < NITER) issue(it + 1, (it + 1) & 1);

        const uint32_t sbase = smb + (uint32_t)(it & 1) * (SMG_STAGE * 4);
#pragma unroll
        for (int ks = 0; ks < 4; ks++) {
            const uint32_t ko = (uint32_t)(ks * 32);
            uint32_t af[4][4];
#pragma unroll
            for (int mt = 0; mt < 4; mt++)
                ldsm_x4(af[mt][0], af[mt][1], af[mt][2], af[mt][3], sbase + aoff[mt] + ko);
#pragma unroll
            for (int p = 0; p < 4; p++) {
                uint32_t bb0, bb1, bb2, bb3;
                ldsm_x4(bb0, bb1, bb2, bb3, sbase + boff[p] + ko);
#pragma unroll
                for (int mt = 0; mt < 4; mt++) {
                    mma_tf32(acc[mt][2*p][0], acc[mt][2*p][1], acc[mt][2*p][2], acc[mt][2*p][3],
                             af[mt][0], af[mt][1], af[mt][2], af[mt][3], bb0, bb1);
                    mma_tf32(acc[mt][2*p+1][0], acc[mt][2*p+1][1], acc[mt][2*p+1][2], acc[mt][2*p+1][3],
                             af[mt][0], af[mt][1], af[mt][2], af[mt][3], bb2, bb3);
                }
            }
        }
    }

    const bool vblock = roundC && (bn >= 2 * DMODEL);
#pragma unroll
    for (int mt = 0; mt < 4; mt++) {
#pragma unroll
        for (int nt = 0; nt < 8; nt++) {
            const int row = bm + wm * 64 + mt * 16 + g;
            const int col = bn + wn * 64 + nt * 8 + j * 2;
            const float bz0 = __ldg(&bias[col]);
            const float bz1 = __ldg(&bias[col + 1]);
            float r00 = acc[mt][nt][0] + bz0, r01 = acc[mt][nt][1] + bz1;
            float r10 = acc[mt][nt][2] + bz0, r11 = acc[mt][nt][3] + bz1;
            if (roundC) {
                const float sc = (col < DMODEL) ? QSCALE : 1.0f;
                r00 = rna_tf32(r00 * sc); r01 = rna_tf32(r01 * sc);
                r10 = rna_tf32(r10 * sc); r11 = rna_tf32(r11 * sc);
            }
            if (vblock) {
                // V: transposed store to g_Vt[b*1024 + (col-2048)][s]
                const int b_ = row >> 11;            // row / SEQ
                const int s_ = row & (SEQ - 1);
                const size_t vr = (size_t)(b_ * DMODEL + col - 2 * DMODEL) * SEQ;
                g_Vt[vr + s_]            = r00;
                g_Vt[vr + SEQ + s_]      = r01;
                g_Vt[vr + s_ + 8]        = r10;
                g_Vt[vr + SEQ + s_ + 8]  = r11;
            } else {
                *(float2*)&C[(size_t)row * Ntot + col] = make_float2(r00, r01);
                *(float2*)&C[(size_t)(row + 8) * Ntot + col] = make_float2(r10, r11);
            }
        }
    }
}

// ============================================================================
// Tensor-core flash attention. V now [d][s] in gmem -> smem tiles [d][c]
// (stride 68, same orientation as K) -> V fragments via ldmatrix, like K.
// Rows 64..79 of Vt tile: row 64 = ones (l column), 65..79 = 0 (junk tile
// p=4 upper half skipped). ONE __syncthreads per KV tile.
// ============================================================================
#define ABR 256
#define ABC 64
#define AST 68
#define OFF_Q  0                         // 256*68 = 17408
#define OFF_K0 17408                     // 64*68 = 4352
#define OFF_K1 21760
#define OFF_V0 26112                     // 80*68 = 5440
#define OFF_V1 31552
#define OFF_P  36992                     // 256*68 = 17408
#define OFF_CP 54400                     // cpen[2][64]
#define ATTN_SMEM ((54400 + 128) * 4)    // 218112 bytes

__global__ __launch_bounds__(256, 1) void attn_mma(const float* __restrict__ mask)
{
    extern __shared__ float sm[];
    const uint32_t smb = smem_u32(sm);
    float* Psm = sm + OFF_P;

    const int t = threadIdx.x, w = t >> 5, lane = t & 31;
    const int g = lane >> 2, j = lane & 3;
    const int bh = blockIdx.y, b = bh >> 4, h = bh & 15;
    const int q0 = blockIdx.x * ABR;

    const float* Qg = g_QKV + (size_t)b * SEQ * NQKV + h * HD;
    const float* Kg = Qg + DMODEL;
    const float* Vtg = g_Vt + ((size_t)b * DMODEL + h * HD) * SEQ;

#pragma unroll
    for (int i = 0; i < 16; i++) {
        int lin = t + i * 256;
        int r = lin >> 4, c4 = (lin & 15) * 4;
        CP_ASYNC16(smb + (uint32_t)(OFF_Q + r * AST + c4) * 4,
                   &Qg[(size_t)(q0 + r) * NQKV + c4]);
    }
    CP_COMMIT();

    // Vt rows 64..79 init (once): row 64 = 1.0 (l column), rows 65..79 = 0
    {
        int r16 = t >> 4, c4 = (t & 15) * 4;
        float v = (r16 == 0) ? 1.0f : 0.0f;
        float4 f = make_float4(v, v, v, v);
        *(float4*)&sm[OFF_V0 + (64 + r16) * AST + c4] = f;
        *(float4*)&sm[OFF_V1 + (64 + r16) * AST + c4] = f;
    }

    auto issue_kv = [&](int kb, int s) {
        const int c0 = kb * ABC;
        const uint32_t kbase = smb + (uint32_t)(s ? OFF_K1 : OFF_K0) * 4;
        const uint32_t vbase = smb + (uint32_t)(s ? OFF_V1 : OFF_V0) * 4;
#pragma unroll
        for (int i = 0; i < 4; i++) {
            int lin = t + i * 256;
            int r = lin >> 4, c4 = (lin & 15) * 4;
            // K rows: tokens [c][d]
            CP_ASYNC16(kbase + (uint32_t)(r * AST + c4) * 4,
                       &Kg[(size_t)(c0 + r) * NQKV + c4]);
            // Vt rows: dims [d][c]
            CP_ASYNC16(vbase + (uint32_t)(r * AST + c4) * 4,
                       &Vtg[(size_t)r * SEQ + c0 + c4]);
        }
        if (t < ABC)
            sm[OFF_CP + s * 64 + t] = -1e6f * L2E * (1.0f - mask[b * SEQ + c0 + t]);
        CP_COMMIT();
    };

    issue_kv(0, 0);

    const int rb = w * 32;
    uint32_t qoff[2], koff[5], poff[2];
    {
        const int arow = lane & 15, acol = (lane >> 4) * 4;
#pragma unroll
        for (int mt = 0; mt < 2; mt++) {
            qoff[mt] = (uint32_t)((OFF_Q + (rb + mt * 16 + arow) * AST + acol) * 4);
            poff[mt] = (uint32_t)((OFF_P + (rb + mt * 16 + arow) * AST + acol) * 4);
        }
        const int brow = ((lane >> 4) & 1) * 8 + (lane & 7);
        const int bcol = ((lane >> 3) & 1) * 4;
#pragma unroll
        for (int p = 0; p < 5; p++)
            koff[p] = (uint32_t)(((p * 16 + brow) * AST + bcol) * 4);
    }

    float mst[2][2] = {{-1e30f, -1e30f}, {-1e30f, -1e30f}};
    float o[2][9][4];     // nt=8 tile col 64 (j=0) accumulates l
#pragma unroll
    for (int mt = 0; mt < 2; mt++)
#pragma unroll
        for (int nt = 0; nt < 9; nt++)
#pragma unroll
            for (int r = 0; r < 4; r++) o[mt][nt][r] = 0.0f;

    const int NB = SEQ / ABC;
    for (int kb = 0; kb < NB; kb++) {
        const int cur = kb & 1;
        CP_WAIT0();
        __syncthreads();
        if (kb + 1 < NB) issue_kv(kb + 1, cur ^ 1);

        const uint32_t kstage = smb + (uint32_t)(cur ? OFF_K1 : OFF_K0) * 4;
        const uint32_t vstage = smb + (uint32_t)(cur ? OFF_V1 : OFF_V0) * 4;
        const float* cp = sm + OFF_CP + cur * 64;

        // ---- S = Q' K^T (log2 units) ----
        float sacc[2][8][4];
#pragma unroll
        for (int mt = 0; mt < 2; mt++)
#pragma unroll
            for (int nt = 0; nt < 8; nt++)
#pragma unroll
                for (int r = 0; r < 4; r++) sacc[mt][nt][r] = 0.0f;

#pragma unroll
        for (int ks = 0; ks < 8; ks++) {
            const uint32_t ko = (uint32_t)(ks * 32);
            uint32_t af[2][4];
#pragma unroll
            for (int mt = 0; mt < 2; mt++)
                ldsm_x4(af[mt][0], af[mt][1], af[mt][2], af[mt][3], smb + qoff[mt] + ko);
#pragma unroll
            for (int p = 0; p < 4; p++) {
                uint32_t b0, b1, b2, b3;
                ldsm_x4(b0, b1, b2, b3, kstage + koff[p] + ko);
#pragma unroll
                for (int mt = 0; mt < 2; mt++) {
                    mma_tf32(sacc[mt][2*p][0], sacc[mt][2*p][1], sacc[mt][2*p][2], sacc[mt][2*p][3],
                             af[mt][0], af[mt][1], af[mt][2], af[mt][3], b0, b1);
                    mma_tf32(sacc[mt][2*p+1][0], sacc[mt][2*p+1][1], sacc[mt][2*p+1][2], sacc[mt][2*p+1][3],
                             af[mt][0], af[mt][1], af[mt][2], af[mt][3], b2, b3);
                }
            }
        }

        // ---- softmax: max + exp only (l from the PV MMA ones column) ----
#pragma unroll
        for (int mt = 0; mt < 2; mt++) {
            float mx0 = -1e30f, mx1 = -1e30f;
#pragma unroll
            for (int nt = 0; nt < 8; nt++) {
                const float p0 = cp[nt * 8 + 2 * j], p1 = cp[nt * 8 + 2 * j + 1];
                sacc[mt][nt][0] += p0;
                sacc[mt][nt][1] += p1;
                sacc[mt][nt][2] += p0;
                sacc[mt][nt][3] += p1;
                mx0 = fmaxf(mx0, fmaxf(sacc[mt][nt][0], sacc[mt][nt][1]));
                mx1 = fmaxf(mx1, fmaxf(sacc[mt][nt][2], sacc[mt][nt][3]));
            }
            mx0 = fmaxf(mx0, __shfl_xor_sync(0xffffffffu, mx0, 1));
            mx0 = fmaxf(mx0, __shfl_xor_sync(0xffffffffu, mx0, 2));
            mx1 = fmaxf(mx1, __shfl_xor_sync(0xffffffffu, mx1, 1));
            mx1 = fmaxf(mx1, __shfl_xor_sync(0xffffffffu, mx1, 2));
            const float mn0 = fmaxf(mst[mt][0], mx0), mn1 = fmaxf(mst[mt][1], mx1);
            const float al0 = ex2(mst[mt][0] - mn0);
            const float al1 = ex2(mst[mt][1] - mn1);
            mst[mt][0] = mn0; mst[mt][1] = mn1;

#pragma unroll
            for (int nt = 0; nt < 9; nt++) {
                o[mt][nt][0] *= al0; o[mt][nt][1] *= al0;
                o[mt][nt][2] *= al1; o[mt][nt][3] *= al1;
            }
#pragma unroll
            for (int nt = 0; nt < 8; nt++) {
                float p00 = ex2(sacc[mt][nt][0] - mn0);
                float p01 = ex2(sacc[mt][nt][1] - mn0);
                float p10 = ex2(sacc[mt][nt][2] - mn1);
                float p11 = ex2(sacc[mt][nt][3] - mn1);
                float* pr = &Psm[(rb + mt * 16 + g) * AST + nt * 8 + 2 * j];
                *(float2*)pr = make_float2(p00, p01);
                *(float2*)(pr + 8 * AST) = make_float2(p10, p11);
            }
        }
        __syncwarp();   // P rows are warp-private

        // ---- [O | l] += P [V | 1] : V fragments via ldmatrix ----
#pragma unroll
        for (int ks = 0; ks < 8; ks++) {
            const uint32_t ko = (uint32_t)(ks * 32);
            uint32_t af[2][4];
#pragma unroll
            for (int mt = 0; mt < 2; mt++)
                ldsm_x4(af[mt][0], af[mt][1], af[mt][2], af[mt][3], smb + poff[mt] + ko);
#pragma unroll
            for (int p = 0; p < 5; p++) {
                uint32_t b0, b1, b2, b3;
                ldsm_x4(b0, b1, b2, b3, vstage + koff[p] + ko);
#pragma unroll
                for (int mt = 0; mt < 2; mt++) {
                    mma_tf32(o[mt][2*p][0], o[mt][2*p][1], o[mt][2*p][2], o[mt][2*p][3],
                             af[mt][0], af[mt][1], af[mt][2], af[mt][3], b0, b1);
                    if (p < 4)
                        mma_tf32(o[mt][2*p+1][0], o[mt][2*p+1][1], o[mt][2*p+1][2], o[mt][2*p+1][3],
                                 af[mt][0], af[mt][1], af[mt][2], af[mt][3], b2, b3);
                }
            }
        }
    }

    // epilogue: l lives in o[mt][8][0]/[2] of j=0 threads -> broadcast in quad
#pragma unroll
    for (int mt = 0; mt < 2; mt++) {
        const float l0 = __shfl_sync(0xffffffffu, o[mt][8][0], lane & 28);
        const float l1 = __shfl_sync(0xffffffffu, o[mt][8][2], lane & 28);
        const float inv0 = 1.0f / l0;
        const float inv1 = 1.0f / l1;
        const size_t row0 = (size_t)(b * SEQ + q0 + rb + mt * 16 + g);
#pragma unroll
        for (int nt = 0; nt < 8; nt++) {
            const int col = h * HD + nt * 8 + 2 * j;
            float2 v0 = make_float2(rna_tf32(o[mt][nt][0] * inv0), rna_tf32(o[mt][nt][1] * inv0));
            float2 v1 = make_float2(rna_tf32(o[mt][nt][2] * inv1), rna_tf32(o[mt][nt][3] * inv1));
            *(float2*)&g_C[row0 * DMODEL + col] = v0;
            *(float2*)&g_C[(row0 + 8) * DMODEL + col] = v1;
        }
    }
}

// ============================================================================
// fused prep: round X | transpose+round weights | concat bias (one launch)
// ============================================================================
#define PREP_X_BLOCKS (MROWS * DMODEL / 256)         // 16384
#define PREP_T_BLOCKS 4096
#define PREP_B_BLOCKS (NQKV / 256)                   // 12

__global__ void prep_all(const float* __restrict__ X,
                         const float* __restrict__ Wq, const float* __restrict__ Wk,
                         const float* __restrict__ Wv, const float* __restrict__ Wo,
                         const float* __restrict__ bq, const float* __restrict__ bk,
                         const float* __restrict__ bv)
{
    const int bid = blockIdx.x;
    const int t = threadIdx.x;
    if (bid < PREP_X_BLOCKS) {
        int i = bid * 256 + t;
        g_A[i] = rna_tf32(X[i]);
    } else if (bid < PREP_X_BLOCKS + PREP_T_BLOCKS) {
        __shared__ float tile[32][33];
        const int r = bid - PREP_X_BLOCKS;
        const int z = r >> 10;
        const int rr = r & 1023;
        const int n0 = (rr & 31) * 32, k0 = (rr >> 5) * 32;
        const float* W = (z == 0) ? Wq : (z == 1) ? Wk : (z == 2) ? Wv : Wo;
        float* Dst = (z == 3) ? g_WtO : (g_WtQKV + (size_t)z * DMODEL * DMODEL);
        const int tx = t & 31, ty0 = t >> 5;
#pragma unroll
        for (int ty = ty0; ty < 32; ty += 8)
            tile[ty][tx] = rna_tf32(W[(size_t)(k0 + ty) * DMODEL + n0 + tx]);
        __syncthreads();
#pragma unroll
        for (int ty = ty0; ty < 32; ty += 8)
            Dst[(size_t)(n0 + ty) * DMODEL + k0 + tx] = tile[tx][ty];
    } else {
        int i = (bid - PREP_X_BLOCKS - PREP_T_BLOCKS) * 256 + t;
        g_biasQKV[i] = (i < 1024) ? bq[i] : (i < 2048) ? bk[i - 1024] : bv[i - 2048];
    }
}

// ============================================================================
extern "C" void kernel_launch(void* const* d_in, const int* in_sizes, int n_in,
                              void* d_out, int out_size)
{
    const float* X    = (const float*)d_in[0];
    const float* mask = (const float*)d_in[1];
    const float* Wq   = (const float*)d_in[2];
    const float* bq   = (const float*)d_in[3];
    const float* Wk   = (const float*)d_in[4];
    const float* bk   = (const float*)d_in[5];
    const float* Wv   = (const float*)d_in[6];
    const float* bv   = (const float*)d_in[7];
    const float* Wo   = (const float*)d_in[8];
    const float* bo   = (const float*)d_in[9];
    float* out = (float*)d_out;

    cudaFuncSetAttribute(gemm_mma, cudaFuncAttributeMaxDynamicSharedMemorySize, GEMM_SMEM);
    cudaFuncSetAttribute(attn_mma, cudaFuncAttributeMaxDynamicSharedMemorySize, ATTN_SMEM);

    float* dA;     cudaGetSymbolAddress((void**)&dA, g_A);
    float* dQKV;   cudaGetSymbolAddress((void**)&dQKV, g_QKV);
    float* dC;     cudaGetSymbolAddress((void**)&dC, g_C);
    float* dWtQKV; cudaGetSymbolAddress((void**)&dWtQKV, g_WtQKV);
    float* dWtO;   cudaGetSymbolAddress((void**)&dWtO, g_WtO);
    float* dBias;  cudaGetSymbolAddress((void**)&dBias, g_biasQKV);

    prep_all<<<PREP_X_BLOCKS + PREP_T_BLOCKS + PREP_B_BLOCKS, 256>>>(
        X, Wq, Wk, Wv, Wo, bq, bk, bv);

    // QKV projection (Q pre-scaled; V written transposed to g_Vt)
    gemm_mma<<<dim3(NQKV / 128, MROWS / 128), 128, GEMM_SMEM>>>(dA, dWtQKV, dBias, dQKV, NQKV, 1);
    // tensor-core flash attention (ldmatrix V, tensor-core denominator)
    attn_mma<<<dim3(SEQ / ABR, BSZ * NH), 256, ATTN_SMEM>>>(mask);
    // output projection -> d_out
    gemm_mma<<<dim3(DMODEL / 128, MROWS / 128), 128, GEMM_SMEM>>>(dC, dWtO, bo, out, DMODEL, 0);
}